// round 14
// baseline (speedup 1.0000x reference)
#include <cuda_runtime.h>
#include <cuda_bf16.h>
#include <math.h>

#define B_ 8
#define H_ 56
#define W_ 56
#define TOTPTS (B_*65536)
#define FEATTOT (B_*128*H_*W_)
#define BD 256
#define TILE_PTS 512
#define NT (TOTPTS / TILE_PTS)
#define GRID_DEC 152
#define TWOPI 6.28318530717958647692f

// smem byte offsets
#define SB_W1HI 0
#define SB_W1LO 32768
#define SB_W2HI 65536
#define SB_W2LO 73728
#define SB_W3HI 81920
#define SB_W3LO 90112
#define SB_A1HI 98304
#define SB_A1LO 131072
#define SB_B1   163840
#define SB_B2   164096
#define SB_B3   164352
#define SB_W4   164608
#define SB_BG   164864
#define SB_B4   165888
#define SB_TBLW 165904
#define SB_TBLB 174096
#define SB_TBLP 182288
#define SMEM_BYTES 190480

__device__ __align__(128) float g_feat_nhwc[FEATTOT];

__global__ void __launch_bounds__(256) transpose_kernel(const float* __restrict__ f) {
    int idx = blockIdx.x * 256 + threadIdx.x;
    if (idx >= FEATTOT) return;
    int c = idx & 127;
    int rest = idx >> 7;
    int w = rest % W_;
    int r2 = rest / W_;
    int h = r2 % H_;
    int b = r2 / H_;
    g_feat_nhwc[idx] = f[((b * 128 + c) * H_ + h) * W_ + w];
}

__device__ __forceinline__ unsigned smem_u32(const void* p) {
    unsigned a;
    asm("{ .reg .u64 t; cvta.to.shared.u64 t, %1; cvt.u32.u64 %0, t; }" : "=r"(a) : "l"(p));
    return a;
}
__device__ __forceinline__ void ldsm4(unsigned& r0, unsigned& r1, unsigned& r2, unsigned& r3,
                                      unsigned addr) {
    asm volatile("ldmatrix.sync.aligned.m8n8.x4.shared.b16 {%0,%1,%2,%3}, [%4];"
                 : "=r"(r0), "=r"(r1), "=r"(r2), "=r"(r3) : "r"(addr));
}
__device__ __forceinline__ void mma16816(float* c, unsigned a0, unsigned a1, unsigned a2,
                                         unsigned a3, unsigned b0, unsigned b1) {
    asm volatile("mma.sync.aligned.m16n8k16.row.col.f32.bf16.bf16.f32 "
                 "{%0,%1,%2,%3}, {%4,%5,%6,%7}, {%8,%9}, {%0,%1,%2,%3};"
                 : "+f"(c[0]), "+f"(c[1]), "+f"(c[2]), "+f"(c[3])
                 : "r"(a0), "r"(a1), "r"(a2), "r"(a3), "r"(b0), "r"(b1));
}
__device__ __forceinline__ void split2(float a, float b, unsigned& hi, unsigned& lo) {
    __nv_bfloat16 ha = __float2bfloat16(a), hb = __float2bfloat16(b);
    __nv_bfloat162 hp(ha, hb);
    __nv_bfloat162 lp(__float2bfloat16(a - __bfloat162float(ha)),
                      __float2bfloat16(b - __bfloat162float(hb)));
    hi = *(unsigned*)&hp;
    lo = *(unsigned*)&lp;
}
__device__ __forceinline__ void initc2(float (*c0)[4], float (*c1)[4],
                                       const float* bias, int lane) {
    int cq = (lane & 3) * 2;
    #pragma unroll
    for (int j = 0; j < 8; j++) {
        float v0 = bias[j*8 + cq], v1 = bias[j*8 + cq + 1];
        c0[j][0] = v0; c0[j][1] = v1; c0[j][2] = v0; c0[j][3] = v1;
        c1[j][0] = v0; c1[j][1] = v1; c1[j][2] = v0; c1[j][3] = v1;
    }
}

// M=64 K=32 GEMM: A 64 rows x 32 k bf16 (64B rows, chunk^((row>>1)&3) swizzle).
// kc0 reads B k16 slice at kb0, kc1 at kb1 (W1 rows 512B, chunk^(n&7) swizzle).
__device__ __forceinline__ void gemm_m64_k32(
    float (*c0)[4], float (*c1)[4], float (*c2)[4], float (*c3)[4],
    unsigned aHiA, unsigned aLoA, unsigned bHiA, unsigned bLoA,
    int kb0, int kb1, int lane)
{
    float (*cc[4])[4] = {c0, c1, c2, c3};
    int r = lane & 15, kh = lane >> 4;
    int l7 = lane & 7, mat = lane >> 3;
    int khb = mat & 1, jup = (mat >> 1) & 1;
    unsigned akey = (unsigned)((r >> 1) & 3);
    #pragma unroll
    for (int kc = 0; kc < 2; kc++) {
        unsigned ac = (unsigned)(kc*2 + kh);
        unsigned ah[4][4], al[4][4];
        #pragma unroll
        for (int t = 0; t < 4; t++) {
            unsigned aoff = (unsigned)((t*16 + r) * 64) + ((ac ^ akey) * 16u);
            ldsm4(ah[t][0], ah[t][1], ah[t][2], ah[t][3], aHiA + aoff);
            ldsm4(al[t][0], al[t][1], al[t][2], al[t][3], aLoA + aoff);
        }
        int kb = kc ? kb1 : kb0;
        unsigned bc = (unsigned)((kb >> 3) + khb);
        #pragma unroll
        for (int jp = 0; jp < 4; jp++) {
            unsigned n = (unsigned)(((jp*2 + jup) << 3) + l7);
            unsigned boff = (n << 9) + ((bc ^ (n & 7u)) * 16u);
            unsigned bh0, bh1, bh2, bh3, bl0, bl1, bl2, bl3;
            ldsm4(bh0, bh1, bh2, bh3, bHiA + boff);
            ldsm4(bl0, bl1, bl2, bl3, bLoA + boff);
            #pragma unroll
            for (int t = 0; t < 4; t++) {
                mma16816(cc[t][jp*2],   ah[t][0], ah[t][1], ah[t][2], ah[t][3], bh0, bh1);
                mma16816(cc[t][jp*2],   al[t][0], al[t][1], al[t][2], al[t][3], bh0, bh1);
                mma16816(cc[t][jp*2],   ah[t][0], ah[t][1], ah[t][2], ah[t][3], bl0, bl1);
                mma16816(cc[t][jp*2+1], ah[t][0], ah[t][1], ah[t][2], ah[t][3], bh2, bh3);
                mma16816(cc[t][jp*2+1], al[t][0], al[t][1], al[t][2], al[t][3], bh2, bh3);
                mma16816(cc[t][jp*2+1], ah[t][0], ah[t][1], ah[t][2], ah[t][3], bl2, bl3);
            }
        }
    }
}

// M=32 K=64 GEMM (layers 2/3): A 32 rows x 64 k (128B rows, chunk^(r&7)), B rows 128B
__device__ __forceinline__ void gemm_m32(
    float (*c0)[4], float (*c1)[4],
    unsigned aHiA, unsigned aLoA, unsigned bHiA, unsigned bLoA, int lane)
{
    int r = lane & 15, kh = lane >> 4;
    int l7 = lane & 7, mat = lane >> 3;
    int khb = mat & 1, jup = (mat >> 1) & 1;
    #pragma unroll
    for (int kc = 0; kc < 4; kc++) {
        unsigned ac = (unsigned)(kc*2 + kh);
        unsigned aoff = (unsigned)(r*128) + ((ac ^ (unsigned)(r & 7)) * 16u);
        unsigned p0h0, p0h1, p0h2, p0h3, p0l0, p0l1, p0l2, p0l3;
        unsigned p1h0, p1h1, p1h2, p1h3, p1l0, p1l1, p1l2, p1l3;
        ldsm4(p0h0, p0h1, p0h2, p0h3, aHiA + aoff);
        ldsm4(p0l0, p0l1, p0l2, p0l3, aLoA + aoff);
        ldsm4(p1h0, p1h1, p1h2, p1h3, aHiA + aoff + 2048u);
        ldsm4(p1l0, p1l1, p1l2, p1l3, aLoA + aoff + 2048u);
        unsigned bc = (unsigned)(kc*2 + khb);
        #pragma unroll
        for (int jp = 0; jp < 4; jp++) {
            unsigned n = (unsigned)(((jp*2 + jup) << 3) + l7);
            unsigned boff = (n << 7) + ((bc ^ (n & 7u)) * 16u);
            unsigned bh0, bh1, bh2, bh3, bl0, bl1, bl2, bl3;
            ldsm4(bh0, bh1, bh2, bh3, bHiA + boff);
            ldsm4(bl0, bl1, bl2, bl3, bLoA + boff);
            mma16816(c0[jp*2],   p0h0, p0h1, p0h2, p0h3, bh0, bh1);
            mma16816(c0[jp*2],   p0l0, p0l1, p0l2, p0l3, bh0, bh1);
            mma16816(c0[jp*2],   p0h0, p0h1, p0h2, p0h3, bl0, bl1);
            mma16816(c0[jp*2+1], p0h0, p0h1, p0h2, p0h3, bh2, bh3);
            mma16816(c0[jp*2+1], p0l0, p0l1, p0l2, p0l3, bh2, bh3);
            mma16816(c0[jp*2+1], p0h0, p0h1, p0h2, p0h3, bl2, bl3);
            mma16816(c1[jp*2],   p1h0, p1h1, p1h2, p1h3, bh0, bh1);
            mma16816(c1[jp*2],   p1l0, p1l1, p1l2, p1l3, bh0, bh1);
            mma16816(c1[jp*2],   p1h0, p1h1, p1h2, p1h3, bl0, bl1);
            mma16816(c1[jp*2+1], p1h0, p1h1, p1h2, p1h3, bh2, bh3);
            mma16816(c1[jp*2+1], p1l0, p1l1, p1l2, p1l3, bh2, bh3);
            mma16816(c1[jp*2+1], p1h0, p1h1, p1h2, p1h3, bl2, bl3);
        }
    }
}

// relu + split + store one m16 C tile into A rows [mt*16, mt*16+16) (128B-row layout)
__device__ __forceinline__ void relu_store_A(float (*c)[4], char* sc,
                                             unsigned aHiOff, unsigned aLoOff,
                                             int mt, int lane) {
    int r = lane >> 2, sub = (lane & 3) * 4;
    int row0 = mt*16 + r, row1 = row0 + 8;
    unsigned key = (unsigned)(row0 & 7);
    #pragma unroll
    for (int j = 0; j < 8; j++) {
        float v0 = fmaxf(c[j][0], 0.f), v1 = fmaxf(c[j][1], 0.f);
        float v2 = fmaxf(c[j][2], 0.f), v3 = fmaxf(c[j][3], 0.f);
        unsigned h01, l01, h23, l23;
        split2(v0, v1, h01, l01);
        split2(v2, v3, h23, l23);
        unsigned off0 = (unsigned)(row0*128) + (((unsigned)j ^ key) * 16u) + (unsigned)sub;
        unsigned off1 = (unsigned)(row1*128) + (((unsigned)j ^ key) * 16u) + (unsigned)sub;
        *(unsigned*)(sc + aHiOff + off0) = h01;
        *(unsigned*)(sc + aLoOff + off0) = l01;
        *(unsigned*)(sc + aHiOff + off1) = h23;
        *(unsigned*)(sc + aLoOff + off1) = l23;
    }
}

__global__ void __launch_bounds__(BD) decoder_kernel(
    const float* __restrict__ points, const float* __restrict__ kmat,
    const float* __restrict__ rt, const float* __restrict__ Bg,
    const float* __restrict__ W1, const float* __restrict__ b1,
    const float* __restrict__ W2, const float* __restrict__ b2,
    const float* __restrict__ W3, const float* __restrict__ b3,
    const float* __restrict__ W4, const float* __restrict__ b4,
    float* __restrict__ out)
{
    extern __shared__ __align__(16) char sc[];
    unsigned sb = smem_u32(sc);
    int tid = threadIdx.x;
    int lane = tid & 31, wid = tid >> 5;

    // ---- stage weights [n][k] k-contiguous, hi/lo bf16, chunk^n swizzle ----
    for (int t = tid; t < 16384; t += BD) {
        int k = t >> 6, n = t & 63;
        float v = W1[t];
        __nv_bfloat16 hv = __float2bfloat16(v);
        unsigned off = (unsigned)(n*512) + ((((unsigned)(k >> 3)) ^ (unsigned)(n & 7)) * 16u)
                     + (unsigned)((k & 7) * 2);
        *(__nv_bfloat16*)(sc + SB_W1HI + off) = hv;
        *(__nv_bfloat16*)(sc + SB_W1LO + off) = __float2bfloat16(v - __bfloat162float(hv));
    }
    for (int t = tid; t < 4096; t += BD) {
        int k = t >> 6, n = t & 63;
        unsigned off = (unsigned)(n*128) + ((((unsigned)(k >> 3)) ^ (unsigned)(n & 7)) * 16u)
                     + (unsigned)((k & 7) * 2);
        float v2 = W2[t];
        __nv_bfloat16 h2 = __float2bfloat16(v2);
        *(__nv_bfloat16*)(sc + SB_W2HI + off) = h2;
        *(__nv_bfloat16*)(sc + SB_W2LO + off) = __float2bfloat16(v2 - __bfloat162float(h2));
        float v3 = W3[t];
        __nv_bfloat16 h3 = __float2bfloat16(v3);
        *(__nv_bfloat16*)(sc + SB_W3HI + off) = h3;
        *(__nv_bfloat16*)(sc + SB_W3LO + off) = __float2bfloat16(v3 - __bfloat162float(h3));
    }
    if (tid < 64) {
        ((float*)(sc + SB_B1))[tid] = b1[tid];
        ((float*)(sc + SB_B2))[tid] = b2[tid];
        ((float*)(sc + SB_B3))[tid] = b3[tid];
        ((float*)(sc + SB_W4))[tid] = W4[tid];
        ((float*)(sc + SB_BG))[tid*4 + 0] = Bg[tid*3 + 0];
        ((float*)(sc + SB_BG))[tid*4 + 1] = Bg[tid*3 + 1];
        ((float*)(sc + SB_BG))[tid*4 + 2] = Bg[tid*3 + 2];
        ((float*)(sc + SB_BG))[tid*4 + 3] = 0.0f;
    }
    if (tid == 0) *(float*)(sc + SB_B4) = b4[0];
    __syncthreads();

    const float* b1p = (const float*)(sc + SB_B1);
    const float* b2p = (const float*)(sc + SB_B2);
    const float* b3p = (const float*)(sc + SB_B3);
    const float* w4p = (const float*)(sc + SB_W4);
    float b4v = *(const float*)(sc + SB_B4);

    unsigned aHiOff = SB_A1HI + (unsigned)(wid * 4096);
    unsigned aLoOff = SB_A1LO + (unsigned)(wid * 4096);
    unsigned aHiA = sb + aHiOff, aLoA = sb + aLoOff;
    unsigned twOff = SB_TBLW + (unsigned)(wid * 1024);
    unsigned tbOff = SB_TBLB + (unsigned)(wid * 1024);
    unsigned tpOff = SB_TBLP + (unsigned)(wid * 1024);

    for (int tile = blockIdx.x; tile < NT; tile += GRID_DEC) {
        int p0w = tile * TILE_PTS + wid * 64;

        // ---- 1. projection: 2 points per lane ----
        #pragma unroll
        for (int pp = 0; pp < 2; pp++) {
            int pl = lane + pp*32;
            int pidx = p0w + pl;
            int b = pidx >> 16;
            float px = points[pidx*3 + 0];
            float py = points[pidx*3 + 1];
            float pz = points[pidx*3 + 2];
            const float* rtb = rt + b*12;
            const float* kb  = kmat + b*9;
            float c0 = rtb[0]*px + rtb[1]*py + rtb[2]*pz + rtb[3];
            float c1 = rtb[4]*px + rtb[5]*py + rtb[6]*pz + rtb[7];
            float c2 = rtb[8]*px + rtb[9]*py + rtb[10]*pz + rtb[11];
            float i0 = kb[0]*c0 + kb[1]*c1 + kb[2]*c2;
            float i1 = kb[3]*c0 + kb[4]*c1 + kb[5]*c2;
            float i2 = kb[6]*c0 + kb[7]*c1 + kb[8]*c2;
            float zb = i2 + 1e-8f;
            float u = i0 / zb, v = i1 / zb;
            float validf = (i2 > 0.0f) ? 1.0f : 0.0f;
            float un = (2.0f*u + 1.0f) / 56.0f - 1.0f;
            float vn = (2.0f*v + 1.0f) / 56.0f - 1.0f;
            float xp = ((un + 1.0f) * 56.0f - 1.0f) * 0.5f;
            float yp = ((vn + 1.0f) * 56.0f - 1.0f) * 0.5f;
            float x0f = floorf(xp), y0f = floorf(yp);
            float fx = xp - x0f, fy = yp - y0f;
            float gx0 = 1.0f - fx, gy0 = 1.0f - fy;
            int ix0 = (int)x0f, iy0 = (int)y0f;
            int ix1 = ix0 + 1, iy1 = iy0 + 1;
            float m00 = (ix0 >= 0 && ix0 < W_ && iy0 >= 0 && iy0 < H_) ? validf : 0.0f;
            float m10 = (ix1 >= 0 && ix1 < W_ && iy0 >= 0 && iy0 < H_) ? validf : 0.0f;
            float m01 = (ix0 >= 0 && ix0 < W_ && iy1 >= 0 && iy1 < H_) ? validf : 0.0f;
            float m11 = (ix1 >= 0 && ix1 < W_ && iy1 >= 0 && iy1 < H_) ? validf : 0.0f;
            int cx0 = min(max(ix0, 0), W_-1), cx1 = min(max(ix1, 0), W_-1);
            int cy0 = min(max(iy0, 0), H_-1), cy1 = min(max(iy1, 0), H_-1);
            *(float4*)(sc + twOff + pl*16) =
                make_float4(gx0*gy0*m00, fx*gy0*m10, gx0*fy*m01, fx*fy*m11);
            *(int4*)(sc + tbOff + pl*16) =
                make_int4(((b*H_ + cy0)*W_ + cx0) << 7, ((b*H_ + cy0)*W_ + cx1) << 7,
                          ((b*H_ + cy1)*W_ + cx0) << 7, ((b*H_ + cy1)*W_ + cx1) << 7);
            *(float4*)(sc + tpOff + pl*16) = make_float4(px, py, pz, 0.0f);
        }
        __syncwarp();

        float c0[8][4], c1[8][4], c2t[8][4], c3t[8][4];
        initc2(c0, c1, b1p, lane);
        initc2(c2t, c3t, b1p, lane);

        // ---- layer 1: 8 K=32 passes ----
        #pragma unroll 1
        for (int pass = 0; pass < 8; pass++) {
            if (pass < 4) {
                // image features, channels pass*32 .. pass*32+31
                int pl4 = lane >> 3, s = lane & 7;
                unsigned ckey = (unsigned)(s >> 1);
                #pragma unroll 2
                for (int it = 0; it < 16; it++) {
                    int p = it*4 + pl4;
                    float4 wv = *(const float4*)(sc + twOff + p*16);
                    int4 bv = *(const int4*)(sc + tbOff + p*16);
                    int goff = pass*32 + s*4;
                    float4 v0 = *(const float4*)(g_feat_nhwc + bv.x + goff);
                    float4 v1 = *(const float4*)(g_feat_nhwc + bv.y + goff);
                    float4 v2 = *(const float4*)(g_feat_nhwc + bv.z + goff);
                    float4 v3 = *(const float4*)(g_feat_nhwc + bv.w + goff);
                    float a0 = wv.x*v0.x + wv.y*v1.x + wv.z*v2.x + wv.w*v3.x;
                    float a1 = wv.x*v0.y + wv.y*v1.y + wv.z*v2.y + wv.w*v3.y;
                    float a2 = wv.x*v0.z + wv.y*v1.z + wv.z*v2.z + wv.w*v3.z;
                    float a3 = wv.x*v0.w + wv.y*v1.w + wv.z*v2.w + wv.w*v3.w;
                    unsigned h01, l01, h23, l23;
                    split2(a0, a1, h01, l01);
                    split2(a2, a3, h23, l23);
                    unsigned off = (unsigned)(p*64)
                                 + ((ckey ^ (unsigned)((p >> 1) & 3)) * 16u)
                                 + (unsigned)((s & 1) * 8);
                    *(uint2*)(sc + aHiOff + off) = make_uint2(h01, h23);
                    *(uint2*)(sc + aLoOff + off) = make_uint2(l01, l23);
                }
            } else {
                // fourier slice f: sin(m f*16..f*16+15) in k 0..15, cos same m in k 16..31
                int f = pass - 4;
                int ph = lane >> 4, j = lane & 15;
                int m = f*16 + j;
                float4 bg = *(const float4*)(sc + SB_BG + m*16);
                unsigned cs = (unsigned)(j >> 3), ccs = cs + 2u;
                unsigned inb = (unsigned)((2*j) & 15);
                #pragma unroll 2
                for (int it = 0; it < 32; it++) {
                    int p = it*2 + ph;
                    float4 pc = *(const float4*)(sc + tpOff + p*16);
                    float sv, cv;
                    sincosf(TWOPI * (pc.x*bg.x + pc.y*bg.y + pc.z*bg.z), &sv, &cv);
                    __nv_bfloat16 shh = __float2bfloat16(sv);
                    __nv_bfloat16 sll = __float2bfloat16(sv - __bfloat162float(shh));
                    __nv_bfloat16 chh = __float2bfloat16(cv);
                    __nv_bfloat16 cll = __float2bfloat16(cv - __bfloat162float(chh));
                    unsigned pkey = (unsigned)((p >> 1) & 3);
                    unsigned base = (unsigned)(p*64);
                    unsigned offS = base + ((cs  ^ pkey) * 16u) + inb;
                    unsigned offC = base + ((ccs ^ pkey) * 16u) + inb;
                    *(__nv_bfloat16*)(sc + aHiOff + offS) = shh;
                    *(__nv_bfloat16*)(sc + aLoOff + offS) = sll;
                    *(__nv_bfloat16*)(sc + aHiOff + offC) = chh;
                    *(__nv_bfloat16*)(sc + aLoOff + offC) = cll;
                }
            }
            __syncwarp();
            int kb0, kb1;
            if (pass < 4) { kb0 = pass*32; kb1 = pass*32 + 16; }
            else          { int f = pass - 4; kb0 = 128 + f*16; kb1 = 192 + f*16; }
            gemm_m64_k32(c0, c1, c2t, c3t, aHiA, aLoA,
                         sb + SB_W1HI, sb + SB_W1LO, kb0, kb1, lane);
            __syncwarp();
        }

        // ---- layers 2..4 per 32-pt half ----
        #pragma unroll 1
        for (int hf = 0; hf < 2; hf++) {
            float (*ca)[4] = hf ? c2t : c0;
            float (*cb)[4] = hf ? c3t : c1;
            relu_store_A(ca, sc, aHiOff, aLoOff, 0, lane);
            relu_store_A(cb, sc, aHiOff, aLoOff, 1, lane);
            __syncwarp();
            float d0[8][4], d1[8][4];
            initc2(d0, d1, b2p, lane);
            gemm_m32(d0, d1, aHiA, aLoA, sb + SB_W2HI, sb + SB_W2LO, lane);
            __syncwarp();
            relu_store_A(d0, sc, aHiOff, aLoOff, 0, lane);
            relu_store_A(d1, sc, aHiOff, aLoOff, 1, lane);
            __syncwarp();
            initc2(d0, d1, b3p, lane);
            gemm_m32(d0, d1, aHiA, aLoA, sb + SB_W3HI, sb + SB_W3LO, lane);

            // layer 4: dot(relu(h3), W4) + b4
            int r = lane >> 2, cq = (lane & 3) * 2;
            #pragma unroll
            for (int mt = 0; mt < 2; mt++) {
                float (*cf)[4] = (mt == 0) ? d0 : d1;
                float o0 = 0.f, o1 = 0.f;
                #pragma unroll
                for (int j = 0; j < 8; j++) {
                    int col = j*8 + cq;
                    float wa = w4p[col], wb = w4p[col + 1];
                    o0 += fmaxf(cf[j][0], 0.f) * wa + fmaxf(cf[j][1], 0.f) * wb;
                    o1 += fmaxf(cf[j][2], 0.f) * wa + fmaxf(cf[j][3], 0.f) * wb;
                }
                o0 += __shfl_xor_sync(0xFFFFFFFFu, o0, 1);
                o0 += __shfl_xor_sync(0xFFFFFFFFu, o0, 2);
                o1 += __shfl_xor_sync(0xFFFFFFFFu, o1, 1);
                o1 += __shfl_xor_sync(0xFFFFFFFFu, o1, 2);
                if ((lane & 3) == 0) {
                    int pr = p0w + hf*32 + mt*16 + r;
                    out[pr]     = o0 + b4v;
                    out[pr + 8] = o1 + b4v;
                }
            }
            __syncwarp();
        }
    }
}

extern "C" void kernel_launch(void* const* d_in, const int* in_sizes, int n_in,
                              void* d_out, int out_size) {
    const float* features = (const float*)d_in[0];
    const float* points   = (const float*)d_in[1];
    const float* kmat     = (const float*)d_in[2];
    const float* rt       = (const float*)d_in[3];
    const float* Bg       = (const float*)d_in[4];
    const float* W1       = (const float*)d_in[5];
    const float* b1       = (const float*)d_in[6];
    const float* W2       = (const float*)d_in[7];
    const float* b2       = (const float*)d_in[8];
    const float* W3       = (const float*)d_in[9];
    const float* b3       = (const float*)d_in[10];
    const float* W4       = (const float*)d_in[11];
    const float* b4       = (const float*)d_in[12];
    float* out = (float*)d_out;

    transpose_kernel<<<FEATTOT/256, 256>>>(features);

    cudaFuncSetAttribute(decoder_kernel,
                         cudaFuncAttributeMaxDynamicSharedMemorySize, SMEM_BYTES);
    decoder_kernel<<<GRID_DEC, BD, SMEM_BYTES>>>(
        points, kmat, rt, Bg, W1, b1, W2, b2, W3, b3, W4, b4, out);
}

// round 15
// speedup vs baseline: 1.2761x; 1.2761x over previous
#include <cuda_runtime.h>
#include <cuda_bf16.h>
#include <math.h>

#define B_ 8
#define H_ 56
#define W_ 56
#define TOTPTS (B_*65536)
#define FEATTOT (B_*128*H_*W_)
#define BD 384
#define TILE_PTS 384
#define NT ((TOTPTS + TILE_PTS - 1) / TILE_PTS)
#define GRID_DEC 152
#define TWOPI 6.28318530717958647692f

// smem byte offsets
#define SB_W1HI 0
#define SB_W1LO 32768
#define SB_W2HI 65536
#define SB_W2LO 73728
#define SB_W3HI 81920
#define SB_W3LO 90112
#define SB_A1HI 98304
#define SB_A1LO 147456
#define SB_B1   196608
#define SB_B2   196864
#define SB_B3   197120
#define SB_W4   197376
#define SB_BG   197632
#define SB_B4   198656
#define SB_TBLW 198672
#define SB_TBLB 204816
#define SB_TBLP 210960
#define SMEM_BYTES 217104

__device__ __align__(128) float g_feat_nhwc[FEATTOT];

__global__ void __launch_bounds__(256) transpose_kernel(const float* __restrict__ f) {
    int idx = blockIdx.x * 256 + threadIdx.x;
    if (idx >= FEATTOT) return;
    int c = idx & 127;
    int rest = idx >> 7;
    int w = rest % W_;
    int r2 = rest / W_;
    int h = r2 % H_;
    int b = r2 / H_;
    g_feat_nhwc[idx] = f[((b * 128 + c) * H_ + h) * W_ + w];
}

__device__ __forceinline__ unsigned smem_u32(const void* p) {
    unsigned a;
    asm("{ .reg .u64 t; cvta.to.shared.u64 t, %1; cvt.u32.u64 %0, t; }" : "=r"(a) : "l"(p));
    return a;
}
__device__ __forceinline__ void ldsm4(unsigned& r0, unsigned& r1, unsigned& r2, unsigned& r3,
                                      unsigned addr) {
    asm volatile("ldmatrix.sync.aligned.m8n8.x4.shared.b16 {%0,%1,%2,%3}, [%4];"
                 : "=r"(r0), "=r"(r1), "=r"(r2), "=r"(r3) : "r"(addr));
}
// no volatile: lets ptxas schedule/interleave HMMA chains
__device__ __forceinline__ void mma16816(float* c, unsigned a0, unsigned a1, unsigned a2,
                                         unsigned a3, unsigned b0, unsigned b1) {
    asm("mma.sync.aligned.m16n8k16.row.col.f32.bf16.bf16.f32 "
        "{%0,%1,%2,%3}, {%4,%5,%6,%7}, {%8,%9}, {%0,%1,%2,%3};"
        : "+f"(c[0]), "+f"(c[1]), "+f"(c[2]), "+f"(c[3])
        : "r"(a0), "r"(a1), "r"(a2), "r"(a3), "r"(b0), "r"(b1));
}
__device__ __forceinline__ void split2(float a, float b, unsigned& hi, unsigned& lo) {
    __nv_bfloat16 ha = __float2bfloat16(a), hb = __float2bfloat16(b);
    __nv_bfloat162 hp(ha, hb);
    __nv_bfloat162 lp(__float2bfloat16(a - __bfloat162float(ha)),
                      __float2bfloat16(b - __bfloat162float(hb)));
    hi = *(unsigned*)&hp;
    lo = *(unsigned*)&lp;
}
__device__ __forceinline__ void initc2(float (*c0)[4], float (*c1)[4],
                                       const float* bias, int lane) {
    int cq = (lane & 3) * 2;
    #pragma unroll
    for (int j = 0; j < 8; j++) {
        float v0 = bias[j*8 + cq], v1 = bias[j*8 + cq + 1];
        c0[j][0] = v0; c0[j][1] = v1; c0[j][2] = v0; c0[j][3] = v1;
        c1[j][0] = v0; c1[j][1] = v1; c1[j][2] = v0; c1[j][3] = v1;
    }
}

// M=32 GEMM vs W1 (rows 512B): A from smem (32x64 tile, 128B rows, chunk^(r&7)).
// kc 0,1 use kb0; kc 2,3 use kb1. Interleaved term-major mma ordering.
__device__ __forceinline__ void gemm_w1(
    float (*c0)[4], float (*c1)[4],
    unsigned aHiA, unsigned aLoA, unsigned bHiA, unsigned bLoA,
    int kb0, int kb1, int lane)
{
    int r = lane & 15, kh = lane >> 4;
    int l7 = lane & 7, mat = lane >> 3;
    int khb = mat & 1, jup = (mat >> 1) & 1;
    #pragma unroll
    for (int kc = 0; kc < 4; kc++) {
        unsigned ac = (unsigned)((kc & 1)*2 + kh);
        int kb = (kc < 2) ? kb0 : kb1;
        unsigned aoff = (unsigned)(r*128) + (((ac + (unsigned)((kc >> 1)*4)) ^ (unsigned)(r & 7)) * 16u);
        unsigned p0h0, p0h1, p0h2, p0h3, p0l0, p0l1, p0l2, p0l3;
        unsigned p1h0, p1h1, p1h2, p1h3, p1l0, p1l1, p1l2, p1l3;
        ldsm4(p0h0, p0h1, p0h2, p0h3, aHiA + aoff);
        ldsm4(p0l0, p0l1, p0l2, p0l3, aLoA + aoff);
        ldsm4(p1h0, p1h1, p1h2, p1h3, aHiA + aoff + 2048u);
        ldsm4(p1l0, p1l1, p1l2, p1l3, aLoA + aoff + 2048u);
        unsigned bc = (unsigned)((kb >> 3) + (kc & 1)*2 + khb);
        #pragma unroll
        for (int jp = 0; jp < 4; jp++) {
            unsigned n = (unsigned)(((jp*2 + jup) << 3) + l7);
            unsigned boff = (n << 9) + ((bc ^ (n & 7u)) * 16u);
            unsigned bh0, bh1, bh2, bh3, bl0, bl1, bl2, bl3;
            ldsm4(bh0, bh1, bh2, bh3, bHiA + boff);
            ldsm4(bl0, bl1, bl2, bl3, bLoA + boff);
            mma16816(c0[jp*2],   p0h0, p0h1, p0h2, p0h3, bh0, bh1);
            mma16816(c0[jp*2+1], p0h0, p0h1, p0h2, p0h3, bh2, bh3);
            mma16816(c1[jp*2],   p1h0, p1h1, p1h2, p1h3, bh0, bh1);
            mma16816(c1[jp*2+1], p1h0, p1h1, p1h2, p1h3, bh2, bh3);
            mma16816(c0[jp*2],   p0l0, p0l1, p0l2, p0l3, bh0, bh1);
            mma16816(c0[jp*2+1], p0l0, p0l1, p0l2, p0l3, bh2, bh3);
            mma16816(c1[jp*2],   p1l0, p1l1, p1l2, p1l3, bh0, bh1);
            mma16816(c1[jp*2+1], p1l0, p1l1, p1l2, p1l3, bh2, bh3);
            mma16816(c0[jp*2],   p0h0, p0h1, p0h2, p0h3, bl0, bl1);
            mma16816(c0[jp*2+1], p0h0, p0h1, p0h2, p0h3, bl2, bl3);
            mma16816(c1[jp*2],   p1h0, p1h1, p1h2, p1h3, bl0, bl1);
            mma16816(c1[jp*2+1], p1h0, p1h1, p1h2, p1h3, bl2, bl3);
        }
    }
}

// M=32 K=64 GEMM with A fragments in registers (from previous layer's C frags).
// aH01[t][j] = pack(c[j][0],c[j][1]) of m-tile t; aH23 = pack(c[j][2],c[j][3]).
// B rows 128B (W2/W3). Interleaved ordering.
__device__ __forceinline__ void gemm_regA(
    float (*d0)[4], float (*d1)[4],
    const unsigned (*aH01)[8], const unsigned (*aH23)[8],
    const unsigned (*aL01)[8], const unsigned (*aL23)[8],
    unsigned bHiA, unsigned bLoA, int lane)
{
    int l7 = lane & 7, mat = lane >> 3;
    int khb = mat & 1, jup = (mat >> 1) & 1;
    #pragma unroll
    for (int kc = 0; kc < 4; kc++) {
        unsigned a0h0 = aH01[0][2*kc], a0h1 = aH23[0][2*kc];
        unsigned a0h2 = aH01[0][2*kc+1], a0h3 = aH23[0][2*kc+1];
        unsigned a0l0 = aL01[0][2*kc], a0l1 = aL23[0][2*kc];
        unsigned a0l2 = aL01[0][2*kc+1], a0l3 = aL23[0][2*kc+1];
        unsigned a1h0 = aH01[1][2*kc], a1h1 = aH23[1][2*kc];
        unsigned a1h2 = aH01[1][2*kc+1], a1h3 = aH23[1][2*kc+1];
        unsigned a1l0 = aL01[1][2*kc], a1l1 = aL23[1][2*kc];
        unsigned a1l2 = aL01[1][2*kc+1], a1l3 = aL23[1][2*kc+1];
        unsigned bc = (unsigned)(kc*2 + khb);
        #pragma unroll
        for (int jp = 0; jp < 4; jp++) {
            unsigned n = (unsigned)(((jp*2 + jup) << 3) + l7);
            unsigned boff = (n << 7) + ((bc ^ (n & 7u)) * 16u);
            unsigned bh0, bh1, bh2, bh3, bl0, bl1, bl2, bl3;
            ldsm4(bh0, bh1, bh2, bh3, bHiA + boff);
            ldsm4(bl0, bl1, bl2, bl3, bLoA + boff);
            mma16816(d0[jp*2],   a0h0, a0h1, a0h2, a0h3, bh0, bh1);
            mma16816(d0[jp*2+1], a0h0, a0h1, a0h2, a0h3, bh2, bh3);
            mma16816(d1[jp*2],   a1h0, a1h1, a1h2, a1h3, bh0, bh1);
            mma16816(d1[jp*2+1], a1h0, a1h1, a1h2, a1h3, bh2, bh3);
            mma16816(d0[jp*2],   a0l0, a0l1, a0l2, a0l3, bh0, bh1);
            mma16816(d0[jp*2+1], a0l0, a0l1, a0l2, a0l3, bh2, bh3);
            mma16816(d1[jp*2],   a1l0, a1l1, a1l2, a1l3, bh0, bh1);
            mma16816(d1[jp*2+1], a1l0, a1l1, a1l2, a1l3, bh2, bh3);
            mma16816(d0[jp*2],   a0h0, a0h1, a0h2, a0h3, bl0, bl1);
            mma16816(d0[jp*2+1], a0h0, a0h1, a0h2, a0h3, bl2, bl3);
            mma16816(d1[jp*2],   a1h0, a1h1, a1h2, a1h3, bl0, bl1);
            mma16816(d1[jp*2+1], a1h0, a1h1, a1h2, a1h3, bl2, bl3);
        }
    }
}

// relu + bf16-split C frags -> packed A frags (register-only epilogue)
__device__ __forceinline__ void relu_split_frags(
    float (*c0)[4], float (*c1)[4],
    unsigned (*aH01)[8], unsigned (*aH23)[8],
    unsigned (*aL01)[8], unsigned (*aL23)[8])
{
    #pragma unroll
    for (int j = 0; j < 8; j++) {
        split2(fmaxf(c0[j][0], 0.f), fmaxf(c0[j][1], 0.f), aH01[0][j], aL01[0][j]);
        split2(fmaxf(c0[j][2], 0.f), fmaxf(c0[j][3], 0.f), aH23[0][j], aL23[0][j]);
        split2(fmaxf(c1[j][0], 0.f), fmaxf(c1[j][1], 0.f), aH01[1][j], aL01[1][j]);
        split2(fmaxf(c1[j][2], 0.f), fmaxf(c1[j][3], 0.f), aH23[1][j], aL23[1][j]);
    }
}

__global__ void __launch_bounds__(BD) decoder_kernel(
    const float* __restrict__ points, const float* __restrict__ kmat,
    const float* __restrict__ rt, const float* __restrict__ Bg,
    const float* __restrict__ W1, const float* __restrict__ b1,
    const float* __restrict__ W2, const float* __restrict__ b2,
    const float* __restrict__ W3, const float* __restrict__ b3,
    const float* __restrict__ W4, const float* __restrict__ b4,
    float* __restrict__ out)
{
    extern __shared__ __align__(16) char sc[];
    unsigned sb = smem_u32(sc);
    int tid = threadIdx.x;
    int lane = tid & 31, wid = tid >> 5;

    // ---- stage weights [n][k] k-contiguous, hi/lo bf16, chunk^n swizzle ----
    for (int t = tid; t < 16384; t += BD) {
        int k = t >> 6, n = t & 63;
        float v = W1[t];
        __nv_bfloat16 hv = __float2bfloat16(v);
        unsigned off = (unsigned)(n*512) + ((((unsigned)(k >> 3)) ^ (unsigned)(n & 7)) * 16u)
                     + (unsigned)((k & 7) * 2);
        *(__nv_bfloat16*)(sc + SB_W1HI + off) = hv;
        *(__nv_bfloat16*)(sc + SB_W1LO + off) = __float2bfloat16(v - __bfloat162float(hv));
    }
    for (int t = tid; t < 4096; t += BD) {
        int k = t >> 6, n = t & 63;
        unsigned off = (unsigned)(n*128) + ((((unsigned)(k >> 3)) ^ (unsigned)(n & 7)) * 16u)
                     + (unsigned)((k & 7) * 2);
        float v2 = W2[t];
        __nv_bfloat16 h2 = __float2bfloat16(v2);
        *(__nv_bfloat16*)(sc + SB_W2HI + off) = h2;
        *(__nv_bfloat16*)(sc + SB_W2LO + off) = __float2bfloat16(v2 - __bfloat162float(h2));
        float v3 = W3[t];
        __nv_bfloat16 h3 = __float2bfloat16(v3);
        *(__nv_bfloat16*)(sc + SB_W3HI + off) = h3;
        *(__nv_bfloat16*)(sc + SB_W3LO + off) = __float2bfloat16(v3 - __bfloat162float(h3));
    }
    if (tid < 64) {
        ((float*)(sc + SB_B1))[tid] = b1[tid];
        ((float*)(sc + SB_B2))[tid] = b2[tid];
        ((float*)(sc + SB_B3))[tid] = b3[tid];
        ((float*)(sc + SB_W4))[tid] = W4[tid];
        ((float*)(sc + SB_BG))[tid*4 + 0] = Bg[tid*3 + 0];
        ((float*)(sc + SB_BG))[tid*4 + 1] = Bg[tid*3 + 1];
        ((float*)(sc + SB_BG))[tid*4 + 2] = Bg[tid*3 + 2];
        ((float*)(sc + SB_BG))[tid*4 + 3] = 0.0f;
    }
    if (tid == 0) *(float*)(sc + SB_B4) = b4[0];
    __syncthreads();

    const float* b1p = (const float*)(sc + SB_B1);
    const float* b2p = (const float*)(sc + SB_B2);
    const float* b3p = (const float*)(sc + SB_B3);
    const float* w4p = (const float*)(sc + SB_W4);
    float b4v = *(const float*)(sc + SB_B4);

    unsigned aHiOff = SB_A1HI + (unsigned)(wid * 4096);
    unsigned aLoOff = SB_A1LO + (unsigned)(wid * 4096);
    unsigned aHiA = sb + aHiOff, aLoA = sb + aLoOff;
    unsigned twOff = SB_TBLW + (unsigned)(wid * 512);
    unsigned tbOff = SB_TBLB + (unsigned)(wid * 512);
    unsigned tpOff = SB_TBLP + (unsigned)(wid * 512);

    int half = lane >> 4, l15 = lane & 15;

    for (int tile = blockIdx.x; tile < NT; tile += GRID_DEC) {
        int p0 = tile * TILE_PTS + wid * 32;

        // ---- 1. projection: 32 lanes, one point each ----
        {
            int pidx = min(p0 + lane, TOTPTS - 1);
            int b = pidx >> 16;
            float px = points[pidx*3 + 0];
            float py = points[pidx*3 + 1];
            float pz = points[pidx*3 + 2];
            const float* rtb = rt + b*12;
            const float* kb  = kmat + b*9;
            float c0 = rtb[0]*px + rtb[1]*py + rtb[2]*pz + rtb[3];
            float c1 = rtb[4]*px + rtb[5]*py + rtb[6]*pz + rtb[7];
            float c2 = rtb[8]*px + rtb[9]*py + rtb[10]*pz + rtb[11];
            float i0 = kb[0]*c0 + kb[1]*c1 + kb[2]*c2;
            float i1 = kb[3]*c0 + kb[4]*c1 + kb[5]*c2;
            float i2 = kb[6]*c0 + kb[7]*c1 + kb[8]*c2;
            float zb = i2 + 1e-8f;
            float u = i0 / zb, v = i1 / zb;
            float validf = (i2 > 0.0f) ? 1.0f : 0.0f;
            float un = (2.0f*u + 1.0f) / 56.0f - 1.0f;
            float vn = (2.0f*v + 1.0f) / 56.0f - 1.0f;
            float xp = ((un + 1.0f) * 56.0f - 1.0f) * 0.5f;
            float yp = ((vn + 1.0f) * 56.0f - 1.0f) * 0.5f;
            float x0f = floorf(xp), y0f = floorf(yp);
            float fx = xp - x0f, fy = yp - y0f;
            float gx0 = 1.0f - fx, gy0 = 1.0f - fy;
            int ix0 = (int)x0f, iy0 = (int)y0f;
            int ix1 = ix0 + 1, iy1 = iy0 + 1;
            float m00 = (ix0 >= 0 && ix0 < W_ && iy0 >= 0 && iy0 < H_) ? validf : 0.0f;
            float m10 = (ix1 >= 0 && ix1 < W_ && iy0 >= 0 && iy0 < H_) ? validf : 0.0f;
            float m01 = (ix0 >= 0 && ix0 < W_ && iy1 >= 0 && iy1 < H_) ? validf : 0.0f;
            float m11 = (ix1 >= 0 && ix1 < W_ && iy1 >= 0 && iy1 < H_) ? validf : 0.0f;
            int cx0 = min(max(ix0, 0), W_-1), cx1 = min(max(ix1, 0), W_-1);
            int cy0 = min(max(iy0, 0), H_-1), cy1 = min(max(iy1, 0), H_-1);
            *(float4*)(sc + twOff + lane*16) =
                make_float4(gx0*gy0*m00, fx*gy0*m10, gx0*fy*m01, fx*fy*m11);
            *(int4*)(sc + tbOff + lane*16) =
                make_int4(((b*H_ + cy0)*W_ + cx0) << 7, ((b*H_ + cy0)*W_ + cx1) << 7,
                          ((b*H_ + cy1)*W_ + cx0) << 7, ((b*H_ + cy1)*W_ + cx1) << 7);
            *(float4*)(sc + tpOff + lane*16) = make_float4(px, py, pz, 0.0f);
        }
        __syncwarp();

        float c0[8][4], c1[8][4];
        initc2(c0, c1, b1p, lane);

        // ---- layer 1: 4 K=64 passes ----
        #pragma unroll 1
        for (int pass = 0; pass < 4; pass++) {
            if (pass < 2) {
                // image features, channels pass*64 .. pass*64+63
                int chunkC = l15 >> 1, sub8 = (l15 & 1) * 8;
                #pragma unroll 2
                for (int it = 0; it < 16; it++) {
                    int p = it*2 + half;
                    float4 wv = *(const float4*)(sc + twOff + p*16);
                    int4 bv = *(const int4*)(sc + tbOff + p*16);
                    int goff = pass*64 + l15*4;
                    float4 v0 = *(const float4*)(g_feat_nhwc + bv.x + goff);
                    float4 v1 = *(const float4*)(g_feat_nhwc + bv.y + goff);
                    float4 v2 = *(const float4*)(g_feat_nhwc + bv.z + goff);
                    float4 v3 = *(const float4*)(g_feat_nhwc + bv.w + goff);
                    float a0 = wv.x*v0.x + wv.y*v1.x + wv.z*v2.x + wv.w*v3.x;
                    float a1 = wv.x*v0.y + wv.y*v1.y + wv.z*v2.y + wv.w*v3.y;
                    float a2 = wv.x*v0.z + wv.y*v1.z + wv.z*v2.z + wv.w*v3.z;
                    float a3 = wv.x*v0.w + wv.y*v1.w + wv.z*v2.w + wv.w*v3.w;
                    unsigned h01, l01, h23, l23;
                    split2(a0, a1, h01, l01);
                    split2(a2, a3, h23, l23);
                    unsigned off = (unsigned)(p*128 + ((chunkC ^ (p & 7)) * 16) + sub8);
                    *(uint2*)(sc + aHiOff + off) = make_uint2(h01, h23);
                    *(uint2*)(sc + aLoOff + off) = make_uint2(l01, l23);
                }
            } else {
                // fourier: pass2 m 0..31, pass3 m 32..63; sin -> k 0..31, cos -> k 32..63
                int mbase = (pass - 2) * 32 + (l15 << 1);
                #pragma unroll 2
                for (int it = 0; it < 16; it++) {
                    int p = it*2 + half;
                    float4 pc = *(const float4*)(sc + tpOff + p*16);
                    float4 bg0 = *(const float4*)(sc + SB_BG + mbase*16);
                    float4 bg1 = *(const float4*)(sc + SB_BG + mbase*16 + 16);
                    float s0, cc0, s1, cc1;
                    sincosf(TWOPI * (pc.x*bg0.x + pc.y*bg0.y + pc.z*bg0.z), &s0, &cc0);
                    sincosf(TWOPI * (pc.x*bg1.x + pc.y*bg1.y + pc.z*bg1.z), &s1, &cc1);
                    unsigned sh, sl, ch, cl;
                    split2(s0, s1, sh, sl);
                    split2(cc0, cc1, ch, cl);
                    unsigned key = (unsigned)(p & 7);
                    unsigned offS = (unsigned)(p*128) + ((((unsigned)(l15 >> 2)) ^ key) * 16u)
                                  + (unsigned)((l15 & 3) * 4);
                    unsigned offC = (unsigned)(p*128) + ((((unsigned)((l15 >> 2) + 4)) ^ key) * 16u)
                                  + (unsigned)((l15 & 3) * 4);
                    *(unsigned*)(sc + aHiOff + offS) = sh;
                    *(unsigned*)(sc + aLoOff + offS) = sl;
                    *(unsigned*)(sc + aHiOff + offC) = ch;
                    *(unsigned*)(sc + aLoOff + offC) = cl;
                }
            }
            __syncwarp();
            int kb0, kb1;
            if (pass == 0)      { kb0 = 0;   kb1 = 32;  }
            else if (pass == 1) { kb0 = 64;  kb1 = 96;  }
            else if (pass == 2) { kb0 = 128; kb1 = 192; }
            else                { kb0 = 160; kb1 = 224; }
            gemm_w1(c0, c1, aHiA, aLoA, sb + SB_W1HI, sb + SB_W1LO, kb0, kb1, lane);
            __syncwarp();
        }

        // ---- layers 2..3 fully register-resident ----
        unsigned aH01[2][8], aH23[2][8], aL01[2][8], aL23[2][8];
        relu_split_frags(c0, c1, aH01, aH23, aL01, aL23);

        float d0[8][4], d1[8][4];
        initc2(d0, d1, b2p, lane);
        gemm_regA(d0, d1, aH01, aH23, aL01, aL23, sb + SB_W2HI, sb + SB_W2LO, lane);

        relu_split_frags(d0, d1, aH01, aH23, aL01, aL23);
        initc2(d0, d1, b3p, lane);
        gemm_regA(d0, d1, aH01, aH23, aL01, aL23, sb + SB_W3HI, sb + SB_W3LO, lane);

        // ---- layer 4: dot(relu(h3), W4) + b4 ----
        {
            int r = lane >> 2, cq = (lane & 3) * 2;
            #pragma unroll
            for (int mt = 0; mt < 2; mt++) {
                float (*cf)[4] = (mt == 0) ? d0 : d1;
                float o0 = 0.f, o1 = 0.f;
                #pragma unroll
                for (int j = 0; j < 8; j++) {
                    int col = j*8 + cq;
                    float wa = w4p[col], wb = w4p[col + 1];
                    o0 += fmaxf(cf[j][0], 0.f) * wa + fmaxf(cf[j][1], 0.f) * wb;
                    o1 += fmaxf(cf[j][2], 0.f) * wa + fmaxf(cf[j][3], 0.f) * wb;
                }
                o0 += __shfl_xor_sync(0xFFFFFFFFu, o0, 1);
                o0 += __shfl_xor_sync(0xFFFFFFFFu, o0, 2);
                o1 += __shfl_xor_sync(0xFFFFFFFFu, o1, 1);
                o1 += __shfl_xor_sync(0xFFFFFFFFu, o1, 2);
                if ((lane & 3) == 0) {
                    int pr = p0 + mt*16 + r;
                    if (pr < TOTPTS)     out[pr]     = o0 + b4v;
                    if (pr + 8 < TOTPTS) out[pr + 8] = o1 + b4v;
                }
            }
        }
        __syncwarp();
    }
}

extern "C" void kernel_launch(void* const* d_in, const int* in_sizes, int n_in,
                              void* d_out, int out_size) {
    const float* features = (const float*)d_in[0];
    const float* points   = (const float*)d_in[1];
    const float* kmat     = (const float*)d_in[2];
    const float* rt       = (const float*)d_in[3];
    const float* Bg       = (const float*)d_in[4];
    const float* W1       = (const float*)d_in[5];
    const float* b1       = (const float*)d_in[6];
    const float* W2       = (const float*)d_in[7];
    const float* b2       = (const float*)d_in[8];
    const float* W3       = (const float*)d_in[9];
    const float* b3       = (const float*)d_in[10];
    const float* W4       = (const float*)d_in[11];
    const float* b4       = (const float*)d_in[12];
    float* out = (float*)d_out;

    transpose_kernel<<<FEATTOT/256, 256>>>(features);

    cudaFuncSetAttribute(decoder_kernel,
                         cudaFuncAttributeMaxDynamicSharedMemorySize, SMEM_BYTES);
    decoder_kernel<<<GRID_DEC, BD, SMEM_BYTES>>>(
        points, kmat, rt, Bg, W1, b1, W2, b2, W3, b3, W4, b4, out);
}

// round 16
// speedup vs baseline: 1.6156x; 1.2660x over previous
#include <cuda_runtime.h>
#include <cuda_fp16.h>
#include <math.h>

#define B_ 8
#define H_ 56
#define W_ 56
#define TOTPTS (B_*65536)
#define FEATTOT (B_*128*H_*W_)
#define BD 384
#define TILE_PTS 384
#define NT ((TOTPTS + TILE_PTS - 1) / TILE_PTS)
#define GRID_DEC 152
#define TWOPI 6.28318530717958647692f

// smem byte offsets (weights are hi-only fp16 now)
#define SB_W1   0        // 32768
#define SB_W2   32768    // 8192
#define SB_W3   40960    // 8192
#define SB_A1HI 49152    // 12 warps x 4096
#define SB_A1LO 98304    // 12 warps x 4096
#define SB_B1   147456
#define SB_B2   147712
#define SB_B3   147968
#define SB_W4   148224
#define SB_BG   148480
#define SB_B4   149504
#define SB_TBLW 149520   // 12 x 512
#define SB_TBLB 155664
#define SB_TBLP 161808
#define SMEM_BYTES 167952

__device__ __align__(128) float g_feat_nhwc[FEATTOT];

__global__ void __launch_bounds__(256) transpose_kernel(const float* __restrict__ f) {
    int idx = blockIdx.x * 256 + threadIdx.x;
    if (idx >= FEATTOT) return;
    int c = idx & 127;
    int rest = idx >> 7;
    int w = rest % W_;
    int r2 = rest / W_;
    int h = r2 % H_;
    int b = r2 / H_;
    g_feat_nhwc[idx] = f[((b * 128 + c) * H_ + h) * W_ + w];
}

__device__ __forceinline__ unsigned smem_u32(const void* p) {
    unsigned a;
    asm("{ .reg .u64 t; cvta.to.shared.u64 t, %1; cvt.u32.u64 %0, t; }" : "=r"(a) : "l"(p));
    return a;
}
__device__ __forceinline__ void ldsm4(unsigned& r0, unsigned& r1, unsigned& r2, unsigned& r3,
                                      unsigned addr) {
    asm volatile("ldmatrix.sync.aligned.m8n8.x4.shared.b16 {%0,%1,%2,%3}, [%4];"
                 : "=r"(r0), "=r"(r1), "=r"(r2), "=r"(r3) : "r"(addr));
}
__device__ __forceinline__ void mma16816(float* c, unsigned a0, unsigned a1, unsigned a2,
                                         unsigned a3, unsigned b0, unsigned b1) {
    asm volatile("mma.sync.aligned.m16n8k16.row.col.f32.f16.f16.f32 "
                 "{%0,%1,%2,%3}, {%4,%5,%6,%7}, {%8,%9}, {%0,%1,%2,%3};"
                 : "+f"(c[0]), "+f"(c[1]), "+f"(c[2]), "+f"(c[3])
                 : "r"(a0), "r"(a1), "r"(a2), "r"(a3), "r"(b0), "r"(b1));
}
// fp16 two-term split: hi = fp16(x), lo = fp16(x - hi); packed pairs
__device__ __forceinline__ void split2h(float a, float b, unsigned& hi, unsigned& lo) {
    __half ha = __float2half_rn(a), hb = __float2half_rn(b);
    __half2 hp = __halves2half2(ha, hb);
    __half2 lp = __halves2half2(__float2half_rn(a - __half2float(ha)),
                                __float2half_rn(b - __half2float(hb)));
    hi = *(unsigned*)&hp;
    lo = *(unsigned*)&lp;
}
__device__ __forceinline__ void initc2(float (*c0)[4], float (*c1)[4],
                                       const float* bias, int lane) {
    int cq = (lane & 3) * 2;
    #pragma unroll
    for (int j = 0; j < 8; j++) {
        float v0 = bias[j*8 + cq], v1 = bias[j*8 + cq + 1];
        c0[j][0] = v0; c0[j][1] = v1; c0[j][2] = v0; c0[j][3] = v1;
        c1[j][0] = v0; c1[j][1] = v1; c1[j][2] = v0; c1[j][3] = v1;
    }
}

// M=32 GEMM, K=64 from the 32x64 A tile (128B rows, chunk^(r&7) swizzle).
// Weights hi-only. kc 0,1 use kb0; kc 2,3 use kb1. brsLog: B row stride log2.
__device__ __forceinline__ void gemm_m32(
    float (*c0)[4], float (*c1)[4],
    unsigned aHiA, unsigned aLoA, unsigned bHA,
    int brsLog, int kb0, int kb1, int lane)
{
    int r = lane & 15, kh = lane >> 4;
    int l7 = lane & 7, mat = lane >> 3;
    int khb = mat & 1, jup = (mat >> 1) & 1;
    #pragma unroll
    for (int kc = 0; kc < 4; kc++) {
        unsigned ac = (unsigned)(kc*2 + kh);
        unsigned aoff = (unsigned)(r*128) + ((ac ^ (unsigned)(r & 7)) * 16u);
        unsigned p0h0, p0h1, p0h2, p0h3, p0l0, p0l1, p0l2, p0l3;
        unsigned p1h0, p1h1, p1h2, p1h3, p1l0, p1l1, p1l2, p1l3;
        ldsm4(p0h0, p0h1, p0h2, p0h3, aHiA + aoff);
        ldsm4(p0l0, p0l1, p0l2, p0l3, aLoA + aoff);
        ldsm4(p1h0, p1h1, p1h2, p1h3, aHiA + aoff + 2048u);
        ldsm4(p1l0, p1l1, p1l2, p1l3, aLoA + aoff + 2048u);
        int kbase = (kc < 2) ? kb0 : kb1;
        unsigned bc = (unsigned)((kbase >> 3) + (kc & 1) * 2 + khb);
        #pragma unroll
        for (int jp = 0; jp < 4; jp++) {
            unsigned n = (unsigned)(((jp*2 + jup) << 3) + l7);
            unsigned boff = (n << brsLog) + ((bc ^ (n & 7u)) * 16u);
            unsigned bh0, bh1, bh2, bh3;
            ldsm4(bh0, bh1, bh2, bh3, bHA + boff);
            mma16816(c0[jp*2],   p0h0, p0h1, p0h2, p0h3, bh0, bh1);
            mma16816(c0[jp*2],   p0l0, p0l1, p0l2, p0l3, bh0, bh1);
            mma16816(c0[jp*2+1], p0h0, p0h1, p0h2, p0h3, bh2, bh3);
            mma16816(c0[jp*2+1], p0l0, p0l1, p0l2, p0l3, bh2, bh3);
            mma16816(c1[jp*2],   p1h0, p1h1, p1h2, p1h3, bh0, bh1);
            mma16816(c1[jp*2],   p1l0, p1l1, p1l2, p1l3, bh0, bh1);
            mma16816(c1[jp*2+1], p1h0, p1h1, p1h2, p1h3, bh2, bh3);
            mma16816(c1[jp*2+1], p1l0, p1l1, p1l2, p1l3, bh2, bh3);
        }
    }
}

// relu + split + store one m16 C tile into A rows [mt*16, mt*16+16) (128B-row layout)
__device__ __forceinline__ void relu_store_A(float (*c)[4], char* sc,
                                             unsigned aHiOff, unsigned aLoOff,
                                             int mt, int lane) {
    int r = lane >> 2, sub = (lane & 3) * 4;
    int row0 = mt*16 + r, row1 = row0 + 8;
    unsigned key = (unsigned)(row0 & 7);
    #pragma unroll
    for (int j = 0; j < 8; j++) {
        float v0 = fmaxf(c[j][0], 0.f), v1 = fmaxf(c[j][1], 0.f);
        float v2 = fmaxf(c[j][2], 0.f), v3 = fmaxf(c[j][3], 0.f);
        unsigned h01, l01, h23, l23;
        split2h(v0, v1, h01, l01);
        split2h(v2, v3, h23, l23);
        unsigned off0 = (unsigned)(row0*128) + (((unsigned)j ^ key) * 16u) + (unsigned)sub;
        unsigned off1 = (unsigned)(row1*128) + (((unsigned)j ^ key) * 16u) + (unsigned)sub;
        *(unsigned*)(sc + aHiOff + off0) = h01;
        *(unsigned*)(sc + aLoOff + off0) = l01;
        *(unsigned*)(sc + aHiOff + off1) = h23;
        *(unsigned*)(sc + aLoOff + off1) = l23;
    }
}

__global__ void __launch_bounds__(BD) decoder_kernel(
    const float* __restrict__ points, const float* __restrict__ kmat,
    const float* __restrict__ rt, const float* __restrict__ Bg,
    const float* __restrict__ W1, const float* __restrict__ b1,
    const float* __restrict__ W2, const float* __restrict__ b2,
    const float* __restrict__ W3, const float* __restrict__ b3,
    const float* __restrict__ W4, const float* __restrict__ b4,
    float* __restrict__ out)
{
    extern __shared__ __align__(16) char sc[];
    unsigned sb = smem_u32(sc);
    int tid = threadIdx.x;
    int lane = tid & 31, wid = tid >> 5;

    // ---- stage weights [n][k] k-contiguous, fp16 hi only, chunk^n swizzle ----
    for (int t = tid; t < 16384; t += BD) {
        int k = t >> 6, n = t & 63;
        unsigned off = (unsigned)(n*512) + ((((unsigned)(k >> 3)) ^ (unsigned)(n & 7)) * 16u)
                     + (unsigned)((k & 7) * 2);
        *(__half*)(sc + SB_W1 + off) = __float2half_rn(W1[t]);
    }
    for (int t = tid; t < 4096; t += BD) {
        int k = t >> 6, n = t & 63;
        unsigned off = (unsigned)(n*128) + ((((unsigned)(k >> 3)) ^ (unsigned)(n & 7)) * 16u)
                     + (unsigned)((k & 7) * 2);
        *(__half*)(sc + SB_W2 + off) = __float2half_rn(W2[t]);
        *(__half*)(sc + SB_W3 + off) = __float2half_rn(W3[t]);
    }
    if (tid < 64) {
        ((float*)(sc + SB_B1))[tid] = b1[tid];
        ((float*)(sc + SB_B2))[tid] = b2[tid];
        ((float*)(sc + SB_B3))[tid] = b3[tid];
        ((float*)(sc + SB_W4))[tid] = W4[tid];
        ((float*)(sc + SB_BG))[tid*4 + 0] = Bg[tid*3 + 0];
        ((float*)(sc + SB_BG))[tid*4 + 1] = Bg[tid*3 + 1];
        ((float*)(sc + SB_BG))[tid*4 + 2] = Bg[tid*3 + 2];
        ((float*)(sc + SB_BG))[tid*4 + 3] = 0.0f;
    }
    if (tid == 0) *(float*)(sc + SB_B4) = b4[0];
    __syncthreads();

    const float* b1p = (const float*)(sc + SB_B1);
    const float* b2p = (const float*)(sc + SB_B2);
    const float* b3p = (const float*)(sc + SB_B3);
    const float* w4p = (const float*)(sc + SB_W4);
    float b4v = *(const float*)(sc + SB_B4);

    unsigned aHiOff = SB_A1HI + (unsigned)(wid * 4096);
    unsigned aLoOff = SB_A1LO + (unsigned)(wid * 4096);
    unsigned aHiA = sb + aHiOff, aLoA = sb + aLoOff;
    unsigned twOff = SB_TBLW + (unsigned)(wid * 512);
    unsigned tbOff = SB_TBLB + (unsigned)(wid * 512);
    unsigned tpOff = SB_TBLP + (unsigned)(wid * 512);

    int half = lane >> 4, l15 = lane & 15;

    for (int tile = blockIdx.x; tile < NT; tile += GRID_DEC) {
        int p0 = tile * TILE_PTS + wid * 32;

        // ---- 1. projection: 32 lanes, one point each ----
        {
            int pidx = min(p0 + lane, TOTPTS - 1);
            int b = pidx >> 16;
            float px = points[pidx*3 + 0];
            float py = points[pidx*3 + 1];
            float pz = points[pidx*3 + 2];
            const float* rtb = rt + b*12;
            const float* kb  = kmat + b*9;
            float c0 = rtb[0]*px + rtb[1]*py + rtb[2]*pz + rtb[3];
            float c1 = rtb[4]*px + rtb[5]*py + rtb[6]*pz + rtb[7];
            float c2 = rtb[8]*px + rtb[9]*py + rtb[10]*pz + rtb[11];
            float i0 = kb[0]*c0 + kb[1]*c1 + kb[2]*c2;
            float i1 = kb[3]*c0 + kb[4]*c1 + kb[5]*c2;
            float i2 = kb[6]*c0 + kb[7]*c1 + kb[8]*c2;
            float zb = i2 + 1e-8f;
            float u = i0 / zb, v = i1 / zb;
            float validf = (i2 > 0.0f) ? 1.0f : 0.0f;
            float un = (2.0f*u + 1.0f) / 56.0f - 1.0f;
            float vn = (2.0f*v + 1.0f) / 56.0f - 1.0f;
            float xp = ((un + 1.0f) * 56.0f - 1.0f) * 0.5f;
            float yp = ((vn + 1.0f) * 56.0f - 1.0f) * 0.5f;
            float x0f = floorf(xp), y0f = floorf(yp);
            float fx = xp - x0f, fy = yp - y0f;
            float gx0 = 1.0f - fx, gy0 = 1.0f - fy;
            int ix0 = (int)x0f, iy0 = (int)y0f;
            int ix1 = ix0 + 1, iy1 = iy0 + 1;
            float m00 = (ix0 >= 0 && ix0 < W_ && iy0 >= 0 && iy0 < H_) ? validf : 0.0f;
            float m10 = (ix1 >= 0 && ix1 < W_ && iy0 >= 0 && iy0 < H_) ? validf : 0.0f;
            float m01 = (ix0 >= 0 && ix0 < W_ && iy1 >= 0 && iy1 < H_) ? validf : 0.0f;
            float m11 = (ix1 >= 0 && ix1 < W_ && iy1 >= 0 && iy1 < H_) ? validf : 0.0f;
            int cx0 = min(max(ix0, 0), W_-1), cx1 = min(max(ix1, 0), W_-1);
            int cy0 = min(max(iy0, 0), H_-1), cy1 = min(max(iy1, 0), H_-1);
            *(float4*)(sc + twOff + lane*16) =
                make_float4(gx0*gy0*m00, fx*gy0*m10, gx0*fy*m01, fx*fy*m11);
            *(int4*)(sc + tbOff + lane*16) =
                make_int4(((b*H_ + cy0)*W_ + cx0) << 7, ((b*H_ + cy0)*W_ + cx1) << 7,
                          ((b*H_ + cy1)*W_ + cx0) << 7, ((b*H_ + cy1)*W_ + cx1) << 7);
            *(float4*)(sc + tpOff + lane*16) = make_float4(px, py, pz, 0.0f);
        }
        __syncwarp();

        float c0[8][4], c1[8][4];
        initc2(c0, c1, b1p, lane);

        // ---- layer 1: 4 K=64 passes ----
        #pragma unroll 1
        for (int pass = 0; pass < 4; pass++) {
            if (pass < 2) {
                // image features, channels pass*64 .. pass*64+63
                int chunkC = l15 >> 1, sub8 = (l15 & 1) * 8;
                #pragma unroll 2
                for (int it = 0; it < 16; it++) {
                    int p = it*2 + half;
                    float4 wv = *(const float4*)(sc + twOff + p*16);
                    int4 bv = *(const int4*)(sc + tbOff + p*16);
                    int goff = pass*64 + l15*4;
                    float4 v0 = *(const float4*)(g_feat_nhwc + bv.x + goff);
                    float4 v1 = *(const float4*)(g_feat_nhwc + bv.y + goff);
                    float4 v2 = *(const float4*)(g_feat_nhwc + bv.z + goff);
                    float4 v3 = *(const float4*)(g_feat_nhwc + bv.w + goff);
                    float a0 = wv.x*v0.x + wv.y*v1.x + wv.z*v2.x + wv.w*v3.x;
                    float a1 = wv.x*v0.y + wv.y*v1.y + wv.z*v2.y + wv.w*v3.y;
                    float a2 = wv.x*v0.z + wv.y*v1.z + wv.z*v2.z + wv.w*v3.z;
                    float a3 = wv.x*v0.w + wv.y*v1.w + wv.z*v2.w + wv.w*v3.w;
                    unsigned h01, l01, h23, l23;
                    split2h(a0, a1, h01, l01);
                    split2h(a2, a3, h23, l23);
                    unsigned off = (unsigned)(p*128 + ((chunkC ^ (p & 7)) * 16) + sub8);
                    *(uint2*)(sc + aHiOff + off) = make_uint2(h01, h23);
                    *(uint2*)(sc + aLoOff + off) = make_uint2(l01, l23);
                }
            } else {
                // fourier: pass2 m 0..31, pass3 m 32..63; sin -> k 0..31, cos -> k 32..63
                int mbase = (pass - 2) * 32 + (l15 << 1);
                #pragma unroll 2
                for (int it = 0; it < 16; it++) {
                    int p = it*2 + half;
                    float4 pc = *(const float4*)(sc + tpOff + p*16);
                    float4 bg0 = *(const float4*)(sc + SB_BG + mbase*16);
                    float4 bg1 = *(const float4*)(sc + SB_BG + mbase*16 + 16);
                    float s0, cc0, s1, cc1;
                    sincosf(TWOPI * (pc.x*bg0.x + pc.y*bg0.y + pc.z*bg0.z), &s0, &cc0);
                    sincosf(TWOPI * (pc.x*bg1.x + pc.y*bg1.y + pc.z*bg1.z), &s1, &cc1);
                    unsigned sh, sl, ch, cl;
                    split2h(s0, s1, sh, sl);
                    split2h(cc0, cc1, ch, cl);
                    unsigned key = (unsigned)(p & 7);
                    unsigned offS = (unsigned)(p*128) + ((((unsigned)(l15 >> 2)) ^ key) * 16u)
                                  + (unsigned)((l15 & 3) * 4);
                    unsigned offC = (unsigned)(p*128) + ((((unsigned)((l15 >> 2) + 4)) ^ key) * 16u)
                                  + (unsigned)((l15 & 3) * 4);
                    *(unsigned*)(sc + aHiOff + offS) = sh;
                    *(unsigned*)(sc + aLoOff + offS) = sl;
                    *(unsigned*)(sc + aHiOff + offC) = ch;
                    *(unsigned*)(sc + aLoOff + offC) = cl;
                }
            }
            __syncwarp();
            int kb0, kb1;
            if (pass == 0)      { kb0 = 0;   kb1 = 32;  }
            else if (pass == 1) { kb0 = 64;  kb1 = 96;  }
            else if (pass == 2) { kb0 = 128; kb1 = 192; }
            else                { kb0 = 160; kb1 = 224; }
            gemm_m32(c0, c1, aHiA, aLoA, sb + SB_W1, 9, kb0, kb1, lane);
            __syncwarp();
        }

        // ---- epilogue 1 -> A2, layer 2 ----
        relu_store_A(c0, sc, aHiOff, aLoOff, 0, lane);
        relu_store_A(c1, sc, aHiOff, aLoOff, 1, lane);
        __syncwarp();
        initc2(c0, c1, b2p, lane);
        gemm_m32(c0, c1, aHiA, aLoA, sb + SB_W2, 7, 0, 32, lane);
        __syncwarp();

        // ---- epilogue 2 -> A2, layer 3 ----
        relu_store_A(c0, sc, aHiOff, aLoOff, 0, lane);
        relu_store_A(c1, sc, aHiOff, aLoOff, 1, lane);
        __syncwarp();
        initc2(c0, c1, b3p, lane);
        gemm_m32(c0, c1, aHiA, aLoA, sb + SB_W3, 7, 0, 32, lane);

        // ---- layer 4: dot(relu(h3), W4) + b4 ----
        {
            int r = lane >> 2, cq = (lane & 3) * 2;
            #pragma unroll
            for (int mt = 0; mt < 2; mt++) {
                float (*cf)[4] = (mt == 0) ? c0 : c1;
                float o0 = 0.f, o1 = 0.f;
                #pragma unroll
                for (int j = 0; j < 8; j++) {
                    int col = j*8 + cq;
                    float wa = w4p[col], wb = w4p[col + 1];
                    o0 += fmaxf(cf[j][0], 0.f) * wa + fmaxf(cf[j][1], 0.f) * wb;
                    o1 += fmaxf(cf[j][2], 0.f) * wa + fmaxf(cf[j][3], 0.f) * wb;
                }
                o0 += __shfl_xor_sync(0xFFFFFFFFu, o0, 1);
                o0 += __shfl_xor_sync(0xFFFFFFFFu, o0, 2);
                o1 += __shfl_xor_sync(0xFFFFFFFFu, o1, 1);
                o1 += __shfl_xor_sync(0xFFFFFFFFu, o1, 2);
                if ((lane & 3) == 0) {
                    int pr = p0 + mt*16 + r;
                    if (pr < TOTPTS)     out[pr]     = o0 + b4v;
                    if (pr + 8 < TOTPTS) out[pr + 8] = o1 + b4v;
                }
            }
        }
        __syncwarp();
    }
}

extern "C" void kernel_launch(void* const* d_in, const int* in_sizes, int n_in,
                              void* d_out, int out_size) {
    const float* features = (const float*)d_in[0];
    const float* points   = (const float*)d_in[1];
    const float* kmat     = (const float*)d_in[2];
    const float* rt       = (const float*)d_in[3];
    const float* Bg       = (const float*)d_in[4];
    const float* W1       = (const float*)d_in[5];
    const float* b1       = (const float*)d_in[6];
    const float* W2       = (const float*)d_in[7];
    const float* b2       = (const float*)d_in[8];
    const float* W3       = (const float*)d_in[9];
    const float* b3       = (const float*)d_in[10];
    const float* W4       = (const float*)d_in[11];
    const float* b4       = (const float*)d_in[12];
    float* out = (float*)d_out;

    transpose_kernel<<<FEATTOT/256, 256>>>(features);

    cudaFuncSetAttribute(decoder_kernel,
                         cudaFuncAttributeMaxDynamicSharedMemorySize, SMEM_BYTES);
    decoder_kernel<<<GRID_DEC, BD, SMEM_BYTES>>>(
        points, kmat, rt, Bg, W1, b1, W2, b2, W3, b3, W4, b4, out);
}